// round 1
// baseline (speedup 1.0000x reference)
#include <cuda_runtime.h>
#include <cstdint>

// Problem constants (fixed shapes from reference)
#define BB 32
#define TT 2048
#define NN 128
#define BN (BB * NN)          // 4096
#define KP 5
#define PMAX 512
#define MINP 2
#define TILES_ELEMS ((size_t)BN * KP * TT)   // 41,943,040
#define EXTRA_ELEMS (BN * KP * 2)            // 40,960

// Scratch (device globals — no allocations allowed)
__device__ float g_seqs[(size_t)BN * TT];    // 32 MB
__device__ int   g_take[BN * KP];

// ---------------------------------------------------------------------------
// Kernel 1: transpose x[b,t,n] -> seqs[b*N+n, t]
// ---------------------------------------------------------------------------
__global__ void transpose_kernel(const float* __restrict__ x, float* __restrict__ seqs) {
    __shared__ float tile[32][33];
    const int b = blockIdx.z;
    const int tBase = blockIdx.x * 32;   // along T
    const int nBase = blockIdx.y * 32;   // along N
    const int tx = threadIdx.x;          // 0..31
    const int ty = threadIdx.y;          // 0..7

    const float* src = x + (size_t)b * TT * NN;
#pragma unroll
    for (int j = 0; j < 32; j += 8) {
        tile[ty + j][tx] = src[(size_t)(tBase + ty + j) * NN + (nBase + tx)];
    }
    __syncthreads();
#pragma unroll
    for (int j = 0; j < 32; j += 8) {
        seqs[(size_t)(b * NN + nBase + ty + j) * TT + (tBase + tx)] = tile[tx][ty + j];
    }
}

// ---------------------------------------------------------------------------
// Kernel 2: per-series 2048-pt FFT -> mag^2 (bins 1..1024) -> top-5 ->
//           period/cycle math. One block per series, 256 threads.
// ---------------------------------------------------------------------------
__global__ void __launch_bounds__(256)
fft_topk_kernel(const float* __restrict__ seqs,
                int* __restrict__ take_out,
                float* __restrict__ out_extra,   // periods then cycles (may be null)
                int write_extras) {
    __shared__ float sre[TT];
    __shared__ float sim[TT];
    __shared__ float ctre[1024];   // twiddle cos, later reused as mag^2
    __shared__ float ctim[1024];   // twiddle sin
    __shared__ float rv[256];
    __shared__ int   ri[256];

    const int bn  = blockIdx.x;
    const int tid = threadIdx.x;
    const float* src = seqs + (size_t)bn * TT;

    // bit-reversed load (11 bits), imag = 0
    for (int i = tid; i < TT; i += 256) {
        int j = __brev((unsigned)i) >> 21;
        sre[j] = src[i];
    }
    for (int i = tid; i < TT; i += 256) sim[i] = 0.0f;
    // twiddles: w_r = exp(-2*pi*i*r/2048), r in [0,1024)
    for (int r = tid; r < 1024; r += 256) {
        float s, c;
        sincospif(-(float)r / 1024.0f, &s, &c);
        ctre[r] = c;
        ctim[r] = s;
    }
    __syncthreads();

    // radix-2 DIT, 11 stages
#pragma unroll 1
    for (int s = 1; s <= 11; ++s) {
        const int half  = 1 << (s - 1);
        const int shift = 11 - s;
#pragma unroll
        for (int jj = 0; jj < 4; ++jj) {
            int j   = tid + jj * 256;           // 0..1023
            int pos = j & (half - 1);
            int i1  = ((j >> (s - 1)) << s) + pos;
            int i2  = i1 + half;
            int r   = pos << shift;
            float wr = ctre[r], wi = ctim[r];
            float br = sre[i2], bi = sim[i2];
            float tr = wr * br - wi * bi;
            float ti = wr * bi + wi * br;
            float ar = sre[i1], ai = sim[i1];
            sre[i1] = ar + tr;  sim[i1] = ai + ti;
            sre[i2] = ar - tr;  sim[i2] = ai - ti;
        }
        __syncthreads();
    }

    // mag^2 for bins 1..1024 stored at ctre[bin-1]
    for (int i = tid; i < 1024; i += 256) {
        int bin = i + 1;
        float re = sre[bin], im = sim[bin];
        ctre[i] = re * re + im * im;
    }
    __syncthreads();

    // top-5 via 5 sequential argmax reductions (tie -> smaller index, like lax.top_k)
    for (int kk = 0; kk < KP; ++kk) {
        float bv = -1.0f; int bi = 0;
        for (int i = tid; i < 1024; i += 256) {
            float v = ctre[i];
            if (v > bv || (v == bv && i < bi)) { bv = v; bi = i; }
        }
        rv[tid] = bv; ri[tid] = bi;
        __syncthreads();
        for (int s2 = 128; s2 > 0; s2 >>= 1) {
            if (tid < s2) {
                float v2 = rv[tid + s2]; int i2 = ri[tid + s2];
                if (v2 > rv[tid] || (v2 == rv[tid] && i2 < ri[tid])) {
                    rv[tid] = v2; ri[tid] = i2;
                }
            }
            __syncthreads();
        }
        if (tid == 0) {
            int idx  = ri[0];
            ctre[idx] = -2.0f;                 // exclude for next round
            int kidx = idx + 1;                // bin index (>=1)
            int period = TT / kidx;
            period = period < PMAX ? period : PMAX;
            period = period > MINP ? period : MINP;
            int cyc = TT / period; if (cyc < 1) cyc = 1;
            take_out[bn * KP + kk] = cyc * period;
            if (write_extras) {
                out_extra[bn * KP + kk]                 = (float)period;
                out_extra[(size_t)BN * KP + bn * KP + kk] = (float)cyc;
            }
        }
        __syncthreads();
    }
}

// ---------------------------------------------------------------------------
// Kernel 3: gather tiles[row, t] = (t < take) ? seqs[bn, T - take + t] : 0
// row = bn*5 + kk. Vectorized float4 stores, scalar loads (L2-resident seqs).
// ---------------------------------------------------------------------------
__global__ void __launch_bounds__(256)
gather_kernel(const float* __restrict__ seqs,
              const int* __restrict__ take,
              float* __restrict__ tiles) {
    const int row = blockIdx.x;              // 0 .. BN*KP-1
    const int bn  = row / KP;
    const int tk  = take[row];
    const int start = TT - tk;
    const float* src = seqs + (size_t)bn * TT;
    float4* dst = reinterpret_cast<float4*>(tiles + (size_t)row * TT);

#pragma unroll
    for (int it = 0; it < 2; ++it) {
        int v  = threadIdx.x + it * 256;     // 0..511
        int t0 = v * 4;
        float4 o;
        o.x = (t0 + 0 < tk) ? src[start + t0 + 0] : 0.0f;
        o.y = (t0 + 1 < tk) ? src[start + t0 + 1] : 0.0f;
        o.z = (t0 + 2 < tk) ? src[start + t0 + 2] : 0.0f;
        o.w = (t0 + 3 < tk) ? src[start + t0 + 3] : 0.0f;
        dst[v] = o;
    }
}

// ---------------------------------------------------------------------------
extern "C" void kernel_launch(void* const* d_in, const int* in_sizes, int n_in,
                              void* d_out, int out_size) {
    const float* x = (const float*)d_in[0];
    float* out = (float*)d_out;

    float* seqs;
    int*   take;
    cudaGetSymbolAddress((void**)&seqs, g_seqs);
    cudaGetSymbolAddress((void**)&take, g_take);

    // 1) transpose to [BN, T]
    {
        dim3 grid(TT / 32, NN / 32, BB);
        dim3 block(32, 8);
        transpose_kernel<<<grid, block>>>(x, seqs);
    }

    // 2) FFT + top-k + period math (+ optional periods/cycles outputs)
    {
        int write_extras = (out_size >= (int)(TILES_ELEMS + EXTRA_ELEMS)) ? 1 : 0;
        float* extra = out + TILES_ELEMS;
        fft_topk_kernel<<<BN, 256>>>(seqs, take, extra, write_extras);
    }

    // 3) gather tiles
    {
        gather_kernel<<<BN * KP, 256>>>(seqs, take, out);
    }
}

// round 2
// speedup vs baseline: 2.6866x; 2.6866x over previous
#include <cuda_runtime.h>
#include <cstdint>

// Problem constants (fixed shapes from reference)
#define BB 32
#define TT 2048
#define NN 128
#define BN (BB * NN)          // 4096
#define KP 5
#define PMAX 512
#define MINP 2
#define TILES_ELEMS ((size_t)BN * KP * TT)   // 41,943,040
#define EXTRA_ELEMS (BN * KP * 2)            // 40,960

// Scratch (device globals — no allocations allowed)
__device__ float g_seqs[(size_t)BN * TT];    // 32 MB
__device__ int   g_take[BN * KP];

// ---------------------------------------------------------------------------
// Kernel 1: transpose x[b,t,n] -> seqs[b*N+n, t]
// ---------------------------------------------------------------------------
__global__ void transpose_kernel(const float* __restrict__ x, float* __restrict__ seqs) {
    __shared__ float tile[32][33];
    const int b = blockIdx.z;
    const int tBase = blockIdx.x * 32;   // along T
    const int nBase = blockIdx.y * 32;   // along N
    const int tx = threadIdx.x;          // 0..31
    const int ty = threadIdx.y;          // 0..7

    const float* src = x + (size_t)b * TT * NN;
#pragma unroll
    for (int j = 0; j < 32; j += 8) {
        tile[ty + j][tx] = src[(size_t)(tBase + ty + j) * NN + (nBase + tx)];
    }
    __syncthreads();
#pragma unroll
    for (int j = 0; j < 32; j += 8) {
        seqs[(size_t)(b * NN + nBase + ty + j) * TT + (tBase + tx)] = tile[tx][ty + j];
    }
}

// ---------------------------------------------------------------------------
// Kernel 2: packed 2-real-in-1-complex 2048-pt Stockham radix-4 FFT.
// One block = TWO series (z = a + i*b). Conjugate-symmetry split gives both
// magnitude spectra. Then top-5 per series (128 threads each) + period math.
// ---------------------------------------------------------------------------
__global__ void __launch_bounds__(256)
fft_topk_kernel(const float* __restrict__ seqs,
                int* __restrict__ take_out,
                float* __restrict__ out_extra,   // periods then cycles (may be null)
                int write_extras) {
    __shared__ float s0r[TT], s0i[TT], s1r[TT], s1i[TT];   // ping-pong complex
    __shared__ float twr[512], twi[512];                   // tw[r]=exp(-2*pi*i*r/2048)
    __shared__ float rv[256];
    __shared__ int   ri[256];

    const int pair = blockIdx.x;          // 0..2047
    const int tid  = threadIdx.x;
    const float* sa = seqs + (size_t)(pair * 2) * TT;
    const float* sb = sa + TT;

    // load: re = series A, im = series B
    for (int i = tid; i < TT; i += 256) { s0r[i] = sa[i]; s0i[i] = sb[i]; }
    for (int r = tid; r < 512; r += 256) {
        float sn, cs; sincospif(-(float)r / 1024.0f, &sn, &cs);
        twr[r] = cs; twi[r] = sn;
    }
    __syncthreads();

    float *xr = s0r, *xi = s0i, *yr = s1r, *yi = s1i;
    int s = 1;
    // 5 Stockham radix-4 passes: n = 2048 -> 512 -> 128 -> 32 -> 8 -> 2
#pragma unroll
    for (int pass = 0; pass < 5; ++pass) {
#pragma unroll
        for (int jj = 0; jj < 2; ++jj) {
            int t  = tid + jj * 256;          // 0..511  (m*s = 512)
            int q  = t & (s - 1);
            int ps = t - q;                   // p*s  (< 512)
            float ar = xr[t],        ai = xi[t];
            float br = xr[t + 512],  bi = xi[t + 512];
            float cr = xr[t + 1024], ci = xi[t + 1024];
            float dr = xr[t + 1536], di = xi[t + 1536];
            float w1r = twr[ps], w1i = twi[ps];
            float w2r = w1r * w1r - w1i * w1i, w2i = 2.0f * w1r * w1i;
            float w3r = w2r * w1r - w2i * w1i, w3i = w2r * w1i + w2i * w1r;
            float apcr = ar + cr, apci = ai + ci;
            float amcr = ar - cr, amci = ai - ci;
            float bpdr = br + dr, bpdi = bi + di;
            float bmdr = br - dr, bmdi = bi - di;
            // r=0
            float y0r = apcr + bpdr, y0i = apci + bpdi;
            // r=1: (amc - i*bmd) * w1
            float t1r = amcr + bmdi, t1i = amci - bmdr;
            // r=2: (apc - bpd) * w2
            float t2r = apcr - bpdr, t2i = apci - bpdi;
            // r=3: (amc + i*bmd) * w3
            float t3r = amcr - bmdi, t3i = amci + bmdr;
            int o = t + 3 * ps;               // q + s*4p
            yr[o]         = y0r;                          yi[o]         = y0i;
            yr[o + s]     = t1r * w1r - t1i * w1i;        yi[o + s]     = t1r * w1i + t1i * w1r;
            yr[o + 2 * s] = t2r * w2r - t2i * w2i;        yi[o + 2 * s] = t2r * w2i + t2i * w2r;
            yr[o + 3 * s] = t3r * w3r - t3i * w3i;        yi[o + 3 * s] = t3r * w3i + t3i * w3r;
        }
        __syncthreads();
        float* tr = xr; xr = yr; yr = tr;
        float* ti = xi; xi = yi; yi = ti;
        s <<= 2;
    }
    // final radix-2 pass (n=2, s=1024, twiddle=1): reads xr(=s1), writes yr(=s0)
#pragma unroll
    for (int jj = 0; jj < 4; ++jj) {
        int t = tid + jj * 256;               // 0..1023
        float ar = xr[t],        ai = xi[t];
        float br = xr[t + 1024], bi = xi[t + 1024];
        yr[t] = ar + br;         yi[t] = ai + bi;
        yr[t + 1024] = ar - br;  yi[t + 1024] = ai - bi;
    }
    __syncthreads();

    // Z in yr/yi. Split packed spectra -> mag^2 for bins 1..1024.
    //   X1[k] = (Z[k] + conj(Z[N-k]))/2 ;  X2[k] = -i(Z[k] - conj(Z[N-k]))/2
    // (constant 1/4 factor dropped — rank-invariant)
    for (int i = tid; i < 1024; i += 256) {
        int k = i + 1, k2 = TT - k;
        float zr = yr[k],  zi = yi[k];
        float ur = yr[k2], ui = yi[k2];
        float x1r = zr + ur, x1i = zi - ui;
        float x2r = zi + ui, x2i = ur - zr;
        xr[i] = x1r * x1r + x1i * x1i;        // mag^2 series A (bin i+1)
        xi[i] = x2r * x2r + x2i * x2i;        // mag^2 series B
    }
    __syncthreads();

    // top-5: threads [0,128) handle series A, [128,256) series B
    const int half = tid >> 7;
    const int ht   = tid & 127;
    float* mag = half ? xi : xr;
    const int bn = pair * 2 + half;

    for (int kk = 0; kk < KP; ++kk) {
        float bv = -1.0f; int bidx = 0;
#pragma unroll
        for (int j = 0; j < 8; ++j) {
            int idx = ht + j * 128;           // ascending -> first (lowest idx) wins ties
            float v = mag[idx];
            if (v > bv) { bv = v; bidx = idx; }
        }
        rv[tid] = bv; ri[tid] = bidx;
        __syncthreads();
        if (ht < 64) {
            float v2 = rv[tid + 64]; int b2 = ri[tid + 64];
            if (v2 > rv[tid] || (v2 == rv[tid] && b2 < ri[tid])) { rv[tid] = v2; ri[tid] = b2; }
        }
        __syncthreads();
        if (ht < 32) {                         // warps 0 and 4 — full warps
            float v = rv[tid]; int b = ri[tid];
            { float v2 = rv[tid + 32]; int b2 = ri[tid + 32];
              if (v2 > v || (v2 == v && b2 < b)) { v = v2; b = b2; } }
#pragma unroll
            for (int off = 16; off; off >>= 1) {
                float v2 = __shfl_down_sync(0xffffffffu, v, off);
                int   b2 = __shfl_down_sync(0xffffffffu, b, off);
                if (v2 > v || (v2 == v && b2 < b)) { v = v2; b = b2; }
            }
            if (ht == 0) {
                mag[b] = -2.0f;                // exclude for next round
                int kidx = b + 1;
                int period = TT / kidx;
                period = period < PMAX ? period : PMAX;
                period = period > MINP ? period : MINP;
                int cyc = TT / period; if (cyc < 1) cyc = 1;
                take_out[bn * KP + kk] = cyc * period;
                if (write_extras) {
                    out_extra[bn * KP + kk]                   = (float)period;
                    out_extra[(size_t)BN * KP + bn * KP + kk] = (float)cyc;
                }
            }
        }
        __syncthreads();
    }
}

// ---------------------------------------------------------------------------
// Kernel 3: gather tiles[row, t] = (t < take) ? seqs[bn, T - take + t] : 0
// ---------------------------------------------------------------------------
__global__ void __launch_bounds__(256)
gather_kernel(const float* __restrict__ seqs,
              const int* __restrict__ take,
              float* __restrict__ tiles) {
    const int row = blockIdx.x;              // 0 .. BN*KP-1
    const int bn  = row / KP;
    const int tk  = take[row];
    const int start = TT - tk;
    const float* src = seqs + (size_t)bn * TT;
    float4* dst = reinterpret_cast<float4*>(tiles + (size_t)row * TT);

#pragma unroll
    for (int it = 0; it < 2; ++it) {
        int v  = threadIdx.x + it * 256;     // 0..511
        int t0 = v * 4;
        float4 o;
        o.x = (t0 + 0 < tk) ? src[start + t0 + 0] : 0.0f;
        o.y = (t0 + 1 < tk) ? src[start + t0 + 1] : 0.0f;
        o.z = (t0 + 2 < tk) ? src[start + t0 + 2] : 0.0f;
        o.w = (t0 + 3 < tk) ? src[start + t0 + 3] : 0.0f;
        dst[v] = o;
    }
}

// ---------------------------------------------------------------------------
extern "C" void kernel_launch(void* const* d_in, const int* in_sizes, int n_in,
                              void* d_out, int out_size) {
    const float* x = (const float*)d_in[0];
    float* out = (float*)d_out;

    float* seqs;
    int*   take;
    cudaGetSymbolAddress((void**)&seqs, g_seqs);
    cudaGetSymbolAddress((void**)&take, g_take);

    // 1) transpose to [BN, T]
    {
        dim3 grid(TT / 32, NN / 32, BB);
        dim3 block(32, 8);
        transpose_kernel<<<grid, block>>>(x, seqs);
    }

    // 2) packed FFT + top-k + period math
    {
        int write_extras = ((size_t)out_size >= (TILES_ELEMS + EXTRA_ELEMS)) ? 1 : 0;
        float* extra = out + TILES_ELEMS;
        fft_topk_kernel<<<BN / 2, 256>>>(seqs, take, extra, write_extras);
    }

    // 3) gather tiles
    {
        gather_kernel<<<BN * KP, 256>>>(seqs, take, out);
    }
}

// round 3
// speedup vs baseline: 3.3222x; 1.2366x over previous
#include <cuda_runtime.h>
#include <cstdint>

// Problem constants (fixed shapes from reference)
#define BB 32
#define TT 2048
#define NN 128
#define BN (BB * NN)          // 4096
#define KP 5
#define PMAX 512
#define MINP 2
#define TILES_ELEMS ((size_t)BN * KP * TT)   // 41,943,040
#define EXTRA_ELEMS (BN * KP * 2)            // 40,960

// Scratch (device global — no allocations allowed)
__device__ float g_seqs[(size_t)BN * TT];    // 32 MB

__device__ __forceinline__ float2 cmul(float2 a, float2 b) {
    return make_float2(a.x * b.x - a.y * b.y, a.x * b.y + a.y * b.x);
}

// ---------------------------------------------------------------------------
// Kernel 1: transpose x[b,t,n] -> seqs[b*N+n, t], 64x64 tiles, float4 both ways
// ---------------------------------------------------------------------------
__global__ void __launch_bounds__(256)
transpose_kernel(const float* __restrict__ x, float* __restrict__ seqs) {
    __shared__ float tile[64][65];
    const int b = blockIdx.z;
    const int tBase = blockIdx.x * 64;   // along T
    const int nBase = blockIdx.y * 64;   // along N
    const int tid = threadIdx.x;
    const float* src = x + (size_t)b * TT * NN;

#pragma unroll
    for (int it = 0; it < 4; ++it) {
        int idx = tid + it * 256;            // 0..1023
        int r = idx >> 4;                    // t offset 0..63
        int c = idx & 15;                    // float4 col along N
        float4 v = *reinterpret_cast<const float4*>(
            src + (size_t)(tBase + r) * NN + nBase + c * 4);
        tile[c * 4 + 0][r] = v.x;
        tile[c * 4 + 1][r] = v.y;
        tile[c * 4 + 2][r] = v.z;
        tile[c * 4 + 3][r] = v.w;
    }
    __syncthreads();
#pragma unroll
    for (int it = 0; it < 4; ++it) {
        int idx = tid + it * 256;
        int r = idx >> 4;                    // n offset 0..63
        int c = idx & 15;                    // float4 col along T
        float4 v;
        v.x = tile[r][c * 4 + 0];
        v.y = tile[r][c * 4 + 1];
        v.z = tile[r][c * 4 + 2];
        v.w = tile[r][c * 4 + 3];
        *reinterpret_cast<float4*>(
            seqs + (size_t)(b * NN + nBase + r) * TT + tBase + c * 4) = v;
    }
}

// ---------------------------------------------------------------------------
// Kernel 2 (fused): packed 2-real-in-1-complex 2048-pt Stockham radix-4 FFT
// -> conjugate-symmetry split -> top-5 per series -> period math -> gather
// (writes all 10 output tile rows with streaming stores). One block = 2 series.
// ---------------------------------------------------------------------------
__global__ void __launch_bounds__(256)
fft_topk_gather_kernel(const float* __restrict__ seqs,
                       float* __restrict__ tiles,
                       float* __restrict__ out_extra,   // periods then cycles
                       int write_extras) {
    __shared__ float2 s0[TT];            // 16 KB
    __shared__ float2 s1[TT];            // 16 KB
    __shared__ float2 tw[512];           // tw[r]=exp(-2*pi*i*r/2048)
    __shared__ float rv[256];
    __shared__ int   ri[256];
    __shared__ int   stake[2 * KP];

    const int pair = blockIdx.x;          // 0..2047
    const int tid  = threadIdx.x;
    const float* sa = seqs + (size_t)(pair * 2) * TT;
    const float* sb = sa + TT;

    // load: re = series A, im = series B
    for (int i = tid; i < TT; i += 256) s0[i] = make_float2(sa[i], sb[i]);
    for (int r = tid; r < 512; r += 256) {
        float sn, cs; sincospif(-(float)r / 1024.0f, &sn, &cs);
        tw[r] = make_float2(cs, sn);
    }
    __syncthreads();

    float2 *xb = s0, *yb = s1;
    int s = 1;
    // 5 Stockham radix-4 passes: n = 2048 -> 512 -> 128 -> 32 -> 8 -> 2
#pragma unroll
    for (int pass = 0; pass < 5; ++pass) {
#pragma unroll
        for (int jj = 0; jj < 2; ++jj) {
            int t  = tid + jj * 256;          // 0..511  (m*s = 512)
            int q  = t & (s - 1);
            int ps = t - q;                   // p*s (< 512)
            float2 a = xb[t];
            float2 b = xb[t + 512];
            float2 c = xb[t + 1024];
            float2 d = xb[t + 1536];
            float2 w1 = tw[ps];
            float2 w2 = make_float2(w1.x * w1.x - w1.y * w1.y, 2.0f * w1.x * w1.y);
            float2 w3 = cmul(w2, w1);
            float2 apc = make_float2(a.x + c.x, a.y + c.y);
            float2 amc = make_float2(a.x - c.x, a.y - c.y);
            float2 bpd = make_float2(b.x + d.x, b.y + d.y);
            float2 bmd = make_float2(b.x - d.x, b.y - d.y);
            float2 y0 = make_float2(apc.x + bpd.x, apc.y + bpd.y);
            float2 t1 = make_float2(amc.x + bmd.y, amc.y - bmd.x);   // amc - i*bmd
            float2 t2 = make_float2(apc.x - bpd.x, apc.y - bpd.y);
            float2 t3 = make_float2(amc.x - bmd.y, amc.y + bmd.x);   // amc + i*bmd
            int o = t + 3 * ps;               // q + s*4p
            yb[o]         = y0;
            yb[o + s]     = cmul(t1, w1);
            yb[o + 2 * s] = cmul(t2, w2);
            yb[o + 3 * s] = cmul(t3, w3);
        }
        __syncthreads();
        float2* tmp = xb; xb = yb; yb = tmp;
        s <<= 2;
    }
    // final radix-2 pass (s=1024, twiddle=1): read xb, write yb
#pragma unroll
    for (int jj = 0; jj < 4; ++jj) {
        int t = tid + jj * 256;               // 0..1023
        float2 a = xb[t];
        float2 b = xb[t + 1024];
        yb[t]        = make_float2(a.x + b.x, a.y + b.y);
        yb[t + 1024] = make_float2(a.x - b.x, a.y - b.y);
    }
    __syncthreads();
    // spectrum Z is in yb; xb is free scratch (4096 floats)
    float* mag = reinterpret_cast<float*>(xb);   // [0,1024)=A, [1024,2048)=B

    // Split packed spectra -> mag^2 for bins 1..1024 (1/4 factor dropped)
    for (int i = tid; i < 1024; i += 256) {
        int k = i + 1, k2 = TT - k;
        float2 z = yb[k];
        float2 u = yb[k2];
        float x1r = z.x + u.x, x1i = z.y - u.y;
        float x2r = z.y + u.y, x2i = u.x - z.x;
        mag[i]        = x1r * x1r + x1i * x1i;   // series A, bin i+1
        mag[1024 + i] = x2r * x2r + x2i * x2i;   // series B
    }
    __syncthreads();

    // top-5: threads [0,128) handle series A, [128,256) series B
    const int half = tid >> 7;
    const int ht   = tid & 127;
    float* magp = mag + half * 1024;
    const int bn = pair * 2 + half;

    for (int kk = 0; kk < KP; ++kk) {
        float bv = -1.0f; int bidx = 0;
#pragma unroll
        for (int j = 0; j < 8; ++j) {
            int idx = ht + j * 128;           // ascending -> lowest idx wins ties
            float v = magp[idx];
            if (v > bv) { bv = v; bidx = idx; }
        }
        rv[tid] = bv; ri[tid] = bidx;
        __syncthreads();
        if (ht < 64) {
            float v2 = rv[tid + 64]; int b2 = ri[tid + 64];
            if (v2 > rv[tid] || (v2 == rv[tid] && b2 < ri[tid])) { rv[tid] = v2; ri[tid] = b2; }
        }
        __syncthreads();
        if (ht < 32) {                         // warps 0 and 4 — full warps
            float v = rv[tid]; int b = ri[tid];
            { float v2 = rv[tid + 32]; int b2 = ri[tid + 32];
              if (v2 > v || (v2 == v && b2 < b)) { v = v2; b = b2; } }
#pragma unroll
            for (int off = 16; off; off >>= 1) {
                float v2 = __shfl_down_sync(0xffffffffu, v, off);
                int   b2 = __shfl_down_sync(0xffffffffu, b, off);
                if (v2 > v || (v2 == v && b2 < b)) { v = v2; b = b2; }
            }
            if (ht == 0) {
                magp[b] = -2.0f;               // exclude for next round
                int kidx = b + 1;
                int period = TT / kidx;
                period = period < PMAX ? period : PMAX;
                period = period > MINP ? period : MINP;
                int cyc = TT / period; if (cyc < 1) cyc = 1;
                stake[half * KP + kk] = cyc * period;
                if (write_extras) {
                    out_extra[bn * KP + kk]                   = (float)period;
                    out_extra[(size_t)BN * KP + bn * KP + kk] = (float)cyc;
                }
            }
        }
        __syncthreads();
    }

    // Fused gather epilogue: write the 10 tile rows for this block's 2 series.
    // tiles row index = bn*KP + kk = pair*10 + r.  Streaming stores (__stcs)
    // keep seqs resident in L2; source reads are L2 hits.
#pragma unroll 1
    for (int r = 0; r < 2 * KP; ++r) {
        const int h2 = r / KP;
        const int tk = stake[r];
        const int start = TT - tk;
        const float* src = seqs + (size_t)(pair * 2 + h2) * TT;
        float4* dst = reinterpret_cast<float4*>(tiles + ((size_t)pair * 2 * KP + r) * TT);
#pragma unroll
        for (int it = 0; it < 2; ++it) {
            int v  = tid + it * 256;          // 0..511
            int t0 = v * 4;
            float4 o;
            o.x = (t0 + 0 < tk) ? src[start + t0 + 0] : 0.0f;
            o.y = (t0 + 1 < tk) ? src[start + t0 + 1] : 0.0f;
            o.z = (t0 + 2 < tk) ? src[start + t0 + 2] : 0.0f;
            o.w = (t0 + 3 < tk) ? src[start + t0 + 3] : 0.0f;
            __stcs(dst + v, o);
        }
    }
}

// ---------------------------------------------------------------------------
extern "C" void kernel_launch(void* const* d_in, const int* in_sizes, int n_in,
                              void* d_out, int out_size) {
    const float* x = (const float*)d_in[0];
    float* out = (float*)d_out;

    float* seqs;
    cudaGetSymbolAddress((void**)&seqs, g_seqs);

    // 1) transpose to [BN, T]
    {
        dim3 grid(TT / 64, NN / 64, BB);
        transpose_kernel<<<grid, 256>>>(x, seqs);
    }

    // 2) fused FFT + top-k + period math + tile gather
    {
        int write_extras = ((size_t)out_size >= (TILES_ELEMS + EXTRA_ELEMS)) ? 1 : 0;
        float* extra = out + TILES_ELEMS;
        fft_topk_gather_kernel<<<BN / 2, 256>>>(seqs, out, extra, write_extras);
    }
}